// round 14
// baseline (speedup 1.0000x reference)
#include <cuda_runtime.h>
#include <math.h>

#define N_NODES 50000
#define N_EDGES 1600000
#define NH      72
#define NFH     152
#define BN_EPS  1e-5f
#define NBUCK   32

typedef unsigned long long u64;

// ---------------- device scratch ----------------
__device__ __align__(16) float g_P[(size_t)N_NODES * NH];
__device__ __align__(16) float g_Q[(size_t)N_NODES * NH];
__device__ __align__(16) float g_agg_h[N_NODES * NH];
__device__ __align__(16) float g_agg_x[N_NODES * 4];
__device__ float g_cnt[N_NODES];
__device__ __align__(16) float g_zh[N_NODES * NH];
__device__ float g_ebuck[NBUCK * 288];
__device__ float g_escale[NH], g_eshift[NH];
__device__ float g_hsum[NH], g_hsq[NH], g_hscale[NH], g_hshift[NH];

__device__ __forceinline__ float psi_f(float p) {
    return copysignf(log1pf(fabsf(p)), p);
}
__device__ __forceinline__ u64 pack2(float f) {
    u64 r; asm("mov.b64 %0, {%1, %1};" : "=l"(r) : "f"(f)); return r;
}
__device__ __forceinline__ u64 pack2f(float a, float b) {
    u64 r; asm("mov.b64 %0, {%1, %2};" : "=l"(r) : "f"(a), "f"(b)); return r;
}
__device__ __forceinline__ void ffma2(u64& d, u64 a, u64 b) {
    asm("fma.rn.f32x2 %0, %1, %2, %0;" : "+l"(d) : "l"(a), "l"(b));
}
__device__ __forceinline__ float2 unpack2(u64 v) {
    float2 r; asm("mov.b64 {%0, %1}, %2;" : "=f"(r.x), "=f"(r.y) : "l"(v)); return r;
}
__device__ __forceinline__ void fma_row(u64* acc, const float* wrow, float f) {
    u64 f2 = pack2(f);
    const ulonglong2* wr = (const ulonglong2*)wrow;
#pragma unroll
    for (int c2 = 0; c2 < 9; ++c2) {
        ulonglong2 w = wr[c2];
        ffma2(acc[2 * c2],     w.x, f2);
        ffma2(acc[2 * c2 + 1], w.y, f2);
    }
}
__device__ __forceinline__ void fma_row2(u64* accA, u64* accB, const float* wrow,
                                         float fA, float fB) {
    u64 a2 = pack2(fA), b2 = pack2(fB);
    const ulonglong2* wr = (const ulonglong2*)wrow;
#pragma unroll
    for (int c2 = 0; c2 < 9; ++c2) {
        ulonglong2 w = wr[c2];
        ffma2(accA[2 * c2],     w.x, a2);
        ffma2(accA[2 * c2 + 1], w.y, a2);
        ffma2(accB[2 * c2],     w.x, b2);
        ffma2(accB[2 * c2 + 1], w.y, b2);
    }
}

// ---------------- K_pre: P/Q precompute + zero accumulators ----------------
__global__ __launch_bounds__(128) void k_pre(const float* __restrict__ h,
                                             const float* __restrict__ We1) {
    __shared__ __align__(16) float sWP[NH * NH];
    __shared__ __align__(16) float sWQ[NH * NH];
    const int tid = threadIdx.x;
    for (int t = tid; t < NH * NH; t += 128) { sWP[t] = We1[t]; sWQ[t] = We1[NH * NH + t]; }

    if (blockIdx.x == 0) {
        for (int t = tid; t < NBUCK * 288; t += 128) g_ebuck[t] = 0.f;
        if (tid < NH) { g_hsum[tid] = 0.f; g_hsq[tid] = 0.f; }
    }
    __syncthreads();

    const int n = blockIdx.x * 64 + (tid >> 1);
    const int half = tid & 1, c0 = half * 36;
    if (n >= N_NODES) return;

    {
        float4 z4 = make_float4(0.f, 0.f, 0.f, 0.f);
        float4* ar = (float4*)(g_agg_h + (size_t)n * NH + c0);
#pragma unroll
        for (int c4 = 0; c4 < 9; ++c4) ar[c4] = z4;
        if (half == 0) {
            *(float4*)(g_agg_x + (size_t)n * 4) = z4;
            g_cnt[n] = 0.f;
        }
    }

    const float4* hr = (const float4*)(h + (size_t)n * NH);
    u64 aP[18], aQ[18];
#pragma unroll
    for (int c = 0; c < 18; ++c) { aP[c] = 0ull; aQ[c] = 0ull; }

#pragma unroll 2
    for (int kc = 0; kc < 18; ++kc) {
        float4 f = hr[kc];
        fma_row(aP, sWP + (kc * 4 + 0) * NH + c0, f.x);
        fma_row(aQ, sWQ + (kc * 4 + 0) * NH + c0, f.x);
        fma_row(aP, sWP + (kc * 4 + 1) * NH + c0, f.y);
        fma_row(aQ, sWQ + (kc * 4 + 1) * NH + c0, f.y);
        fma_row(aP, sWP + (kc * 4 + 2) * NH + c0, f.z);
        fma_row(aQ, sWQ + (kc * 4 + 2) * NH + c0, f.z);
        fma_row(aP, sWP + (kc * 4 + 3) * NH + c0, f.w);
        fma_row(aQ, sWQ + (kc * 4 + 3) * NH + c0, f.w);
    }

    ulonglong2* pr = (ulonglong2*)(g_P + (size_t)n * NH + c0);
    ulonglong2* qr = (ulonglong2*)(g_Q + (size_t)n * NH + c0);
#pragma unroll
    for (int c2 = 0; c2 < 9; ++c2) {
        ulonglong2 o; o.x = aP[2 * c2]; o.y = aP[2 * c2 + 1]; pr[c2] = o;
        ulonglong2 p; p.x = aQ[2 * c2]; p.y = aQ[2 * c2 + 1]; qr[c2] = p;
    }
}

// ---------------- K1g: gather -> z + fused block-reduced BN stats ----------------
__global__ __launch_bounds__(256) void k1g(const float* __restrict__ x,
                                           const int* __restrict__ ei,
                                           const int* __restrict__ ej,
                                           const float* __restrict__ We1,
                                           float* __restrict__ zbuf) {
    __shared__ __align__(16) float sS[2 * NH];
    __shared__ float sSum[144], sSq[144];
    const int tid = threadIdx.x;
    for (int t = tid; t < 2 * NH; t += 256) sS[t] = We1[144 * NH + t];
    if (tid < 144) { sSum[tid] = 0.f; sSq[tid] = 0.f; }
    __syncthreads();

    const int e = tid >> 1, c0 = (tid & 1) * 36;
    const int lane = tid & 31;
    const int ge = blockIdx.x * 128 + e;
    const int i = ei[ge], j = ej[ge];

    float4 xi = *(const float4*)(x + 4 * (size_t)i);
    float4 xj = *(const float4*)(x + 4 * (size_t)j);
    float dx0 = xi.x - xj.x, dx1 = xi.y - xj.y, dx2 = xi.z - xj.z, dx3 = xi.w - xj.w;
    float nw = psi_f(dx0 * dx0 - dx1 * dx1 - dx2 * dx2 - dx3 * dx3);
    float dw = psi_f(xi.x * xj.x - xi.y * xj.y - xi.z * xj.z - xi.w * xj.w);

    const float4* Pr = (const float4*)(g_P + (size_t)i * NH + c0);
    const float4* Qr = (const float4*)(g_Q + (size_t)j * NH + c0);
    float4* zr = (float4*)(zbuf + (size_t)ge * NH + c0);

    float z36[36];
#pragma unroll
    for (int c4 = 0; c4 < 9; ++c4) {
        float4 p = Pr[c4], q = Qr[c4];
        int c = c0 + c4 * 4;
        float z0 = p.x + q.x + nw * sS[c + 0] + dw * sS[NH + c + 0];
        float z1 = p.y + q.y + nw * sS[c + 1] + dw * sS[NH + c + 1];
        float z2 = p.z + q.z + nw * sS[c + 2] + dw * sS[NH + c + 2];
        float z3 = p.w + q.w + nw * sS[c + 3] + dw * sS[NH + c + 3];
        z36[c4 * 4 + 0] = z0; z36[c4 * 4 + 1] = z1;
        z36[c4 * 4 + 2] = z2; z36[c4 * 4 + 3] = z3;
        zr[c4] = make_float4(z0, z1, z2, z3);
    }

#pragma unroll
    for (int c = 0; c < 36; ++c) {
        float s = z36[c];
        float q = s * s;
#pragma unroll
        for (int msk = 2; msk <= 16; msk <<= 1) {
            s += __shfl_xor_sync(0xffffffffu, s, msk);
            q += __shfl_xor_sync(0xffffffffu, q, msk);
        }
        if (lane < 2) {
            atomicAdd(&sSum[c0 + c], s);
            atomicAdd(&sSq[c0 + c], q);
        }
    }
    __syncthreads();

    if (tid < 288) {
        float v = (tid < 144) ? sSum[tid] : sSq[tid - 144];
        atomicAdd(&g_ebuck[(blockIdx.x & (NBUCK - 1)) * 288 + tid], v);
    }
}

// ---------------- BN finalize ----------------
__global__ void kbn_finalize(const float* __restrict__ gamma, const float* __restrict__ beta,
                             float invM, int which) {
    int c = threadIdx.x;
    if (c >= NH) return;
    float s_ = 0.f, q_ = 0.f;
    if (which == 0) {
#pragma unroll 4
        for (int b = 0; b < NBUCK; ++b) {
            s_ += g_ebuck[b * 288 + c];
            q_ += g_ebuck[b * 288 + 144 + c];
        }
    } else {
        s_ = g_hsum[c]; q_ = g_hsq[c];
    }
    float mu  = s_ * invM;
    float var = q_ * invM - mu * mu;
    float sc  = gamma[c] * rsqrtf(var + BN_EPS);
    if (which == 0) { g_escale[c] = sc; g_eshift[c] = beta[c] - mu * sc; }
    else            { g_hscale[c] = sc; g_hshift[c] = beta[c] - mu * sc; }
}

// ---------------- K2a: z -> BN/ReLU -> We2 GEMM -> gate -> m + agg ----------------
__global__ __launch_bounds__(128, 4) void k2a(
        const int* __restrict__ ei,
        const float* __restrict__ We2, const float* __restrict__ be2,
        const float* __restrict__ Wm,  const float* __restrict__ bm,
        float* mout /* z in, m out */) {
    __shared__ __align__(16) float sW[NH * NH];
    __shared__ __align__(16) float sSc[NH], sSh[NH], sBe[NH], sWm[NH];

    const int tid = threadIdx.x;
    for (int t = tid; t < NH * NH; t += 128) sW[t] = We2[t];
    if (tid < NH) {
        sSc[tid] = g_escale[tid]; sSh[tid] = g_eshift[tid];
        sBe[tid] = be2[tid];  sWm[tid] = Wm[tid];
    }
    __syncthreads();

    const int half = tid & 1, c0 = half * 36, cp = c0 ^ 36;
    const int r = tid >> 1;
    const int geA = blockIdx.x * 128 + r;
    const int geB = geA + 64;
    const int iA = ei[geA], iB = ei[geB];

    u64 acc0[18], acc1[18];
#pragma unroll
    for (int c = 0; c < 18; ++c) { acc0[c] = 0ull; acc1[c] = 0ull; }

    {
        const float4* zA4 = (const float4*)(mout + (size_t)geA * NH + c0);
        const float4* zB4 = (const float4*)(mout + (size_t)geB * NH + c0);
        const float4* sc4 = (const float4*)(sSc + c0);
        const float4* sh4 = (const float4*)(sSh + c0);
#pragma unroll 1
        for (int ci = 0; ci < 9; ++ci) {
            float4 za = zA4[ci], zb = zB4[ci];
            float4 sc = sc4[ci], sh = sh4[ci];
            float aA[4], aB[4];
            aA[0] = fmaxf(za.x * sc.x + sh.x, 0.f);
            aA[1] = fmaxf(za.y * sc.y + sh.y, 0.f);
            aA[2] = fmaxf(za.z * sc.z + sh.z, 0.f);
            aA[3] = fmaxf(za.w * sc.w + sh.w, 0.f);
            aB[0] = fmaxf(zb.x * sc.x + sh.x, 0.f);
            aB[1] = fmaxf(zb.y * sc.y + sh.y, 0.f);
            aB[2] = fmaxf(zb.z * sc.z + sh.z, 0.f);
            aB[3] = fmaxf(zb.w * sc.w + sh.w, 0.f);
#pragma unroll
            for (int cc = 0; cc < 4; ++cc) {
                int kk = ci * 4 + cc;
                fma_row2(acc0, acc1, sW + (c0 + kk) * NH + c0, aA[cc], aB[cc]);
                float fA = __shfl_xor_sync(0xffffffffu, aA[cc], 1);
                float fB = __shfl_xor_sync(0xffffffffu, aB[cc], 1);
                fma_row2(acc0, acc1, sW + (cp + kk) * NH + c0, fA, fB);
            }
        }
    }

    float pd0 = 0.f, pd1 = 0.f;
#pragma unroll
    for (int c2 = 0; c2 < 18; ++c2) {
        float2 v0 = unpack2(acc0[c2]);
        float2 v1 = unpack2(acc1[c2]);
        int c = c0 + 2 * c2;
        float e00 = fmaxf(v0.x + sBe[c + 0], 0.f);
        float e01 = fmaxf(v0.y + sBe[c + 1], 0.f);
        float e10 = fmaxf(v1.x + sBe[c + 0], 0.f);
        float e11 = fmaxf(v1.y + sBe[c + 1], 0.f);
        acc0[c2] = pack2f(e00, e01);
        acc1[c2] = pack2f(e10, e11);
        pd0 += e00 * sWm[c + 0] + e01 * sWm[c + 1];
        pd1 += e10 * sWm[c + 0] + e11 * sWm[c + 1];
    }
    pd0 += __shfl_xor_sync(0xffffffffu, pd0, 1);
    pd1 += __shfl_xor_sync(0xffffffffu, pd1, 1);
    float bmv = bm[0];
    float w0 = 1.f / (1.f + expf(-(pd0 + bmv)));
    float w1 = 1.f / (1.f + expf(-(pd1 + bmv)));

    {
        float* mrA = mout + (size_t)geA * NH + c0;
        float* mrB = mout + (size_t)geB * NH + c0;
        float* arA = g_agg_h + (size_t)iA * NH + c0;
        float* arB = g_agg_h + (size_t)iB * NH + c0;
#pragma unroll
        for (int c4 = 0; c4 < 9; ++c4) {
            float2 a0 = unpack2(acc0[2 * c4]);
            float2 a1 = unpack2(acc0[2 * c4 + 1]);
            float2 b0 = unpack2(acc1[2 * c4]);
            float2 b1 = unpack2(acc1[2 * c4 + 1]);
            float4 mA = make_float4(a0.x * w0, a0.y * w0, a1.x * w0, a1.y * w0);
            float4 mB = make_float4(b0.x * w1, b0.y * w1, b1.x * w1, b1.y * w1);
            ((float4*)mrA)[c4] = mA;
            ((float4*)mrB)[c4] = mB;
            atomicAdd((float4*)(arA + c4 * 4), mA);
            atomicAdd((float4*)(arB + c4 * 4), mB);
        }
        if (half == 0) {
            atomicAdd(&g_cnt[iA], 1.f);
            atomicAdd(&g_cnt[iB], 1.f);
        }
    }
}

// ---------------- K2b: m -> Wx1 GEMM -> px -> trans agg ----------------
__global__ __launch_bounds__(128, 4) void k2b(const float* __restrict__ x,
        const int* __restrict__ ei, const int* __restrict__ ej,
        const float* __restrict__ Wx1, const float* __restrict__ bx1,
        const float* __restrict__ Wx2,
        const float* __restrict__ mout) {
    __shared__ __align__(16) float sW[NH * NH];
    __shared__ __align__(16) float sBx[NH], sWx2[NH];

    const int tid = threadIdx.x;
    for (int t = tid; t < NH * NH; t += 128) sW[t] = Wx1[t];
    if (tid < NH) { sBx[tid] = bx1[tid]; sWx2[tid] = Wx2[tid]; }
    __syncthreads();

    const int half = tid & 1, c0 = half * 36, cp = c0 ^ 36;
    const int r = tid >> 1;
    const int geA = blockIdx.x * 128 + r;
    const int geB = geA + 64;

    u64 acc0[18], acc1[18];
#pragma unroll
    for (int c = 0; c < 18; ++c) { acc0[c] = 0ull; acc1[c] = 0ull; }

    {
        const float4* mA4 = (const float4*)(mout + (size_t)geA * NH + c0);
        const float4* mB4 = (const float4*)(mout + (size_t)geB * NH + c0);
#pragma unroll 1
        for (int ci = 0; ci < 9; ++ci) {
            float4 ma = mA4[ci], mb = mB4[ci];
            float aA[4] = {ma.x, ma.y, ma.z, ma.w};
            float aB[4] = {mb.x, mb.y, mb.z, mb.w};
#pragma unroll
            for (int cc = 0; cc < 4; ++cc) {
                int kk = ci * 4 + cc;
                fma_row2(acc0, acc1, sW + (c0 + kk) * NH + c0, aA[cc], aB[cc]);
                float fA = __shfl_xor_sync(0xffffffffu, aA[cc], 1);
                float fB = __shfl_xor_sync(0xffffffffu, aB[cc], 1);
                fma_row2(acc0, acc1, sW + (cp + kk) * NH + c0, fA, fB);
            }
        }
    }

    float px0 = 0.f, px1 = 0.f;
#pragma unroll
    for (int c2 = 0; c2 < 18; ++c2) {
        float2 v0 = unpack2(acc0[c2]);
        float2 v1 = unpack2(acc1[c2]);
        int c = c0 + 2 * c2;
        px0 += fmaxf(v0.x + sBx[c + 0], 0.f) * sWx2[c + 0];
        px0 += fmaxf(v0.y + sBx[c + 1], 0.f) * sWx2[c + 1];
        px1 += fmaxf(v1.x + sBx[c + 0], 0.f) * sWx2[c + 0];
        px1 += fmaxf(v1.y + sBx[c + 1], 0.f) * sWx2[c + 1];
    }
    px0 += __shfl_xor_sync(0xffffffffu, px0, 1);
    px1 += __shfl_xor_sync(0xffffffffu, px1, 1);

    if (half == 0) {
        {
            const int iA = ei[geA], j = ej[geA];
            float4 xi = *(const float4*)(x + 4 * (size_t)iA);
            float4 xj = *(const float4*)(x + 4 * (size_t)j);
            float t0 = fminf(fmaxf((xi.x - xj.x) * px0, -100.f), 100.f);
            float t1 = fminf(fmaxf((xi.y - xj.y) * px0, -100.f), 100.f);
            float t2 = fminf(fmaxf((xi.z - xj.z) * px0, -100.f), 100.f);
            float t3 = fminf(fmaxf((xi.w - xj.w) * px0, -100.f), 100.f);
            atomicAdd((float4*)&g_agg_x[(size_t)iA * 4], make_float4(t0, t1, t2, t3));
        }
        {
            const int iB = ei[geB], j = ej[geB];
            float4 xi = *(const float4*)(x + 4 * (size_t)iB);
            float4 xj = *(const float4*)(x + 4 * (size_t)j);
            float t0 = fminf(fmaxf((xi.x - xj.x) * px1, -100.f), 100.f);
            float t1 = fminf(fmaxf((xi.y - xj.y) * px1, -100.f), 100.f);
            float t2 = fminf(fmaxf((xi.z - xj.z) * px1, -100.f), 100.f);
            float t3 = fminf(fmaxf((xi.w - xj.w) * px1, -100.f), 100.f);
            atomicAdd((float4*)&g_agg_x[(size_t)iB * 4], make_float4(t0, t1, t2, t3));
        }
    }
}

// ---------------- K3a: node pass 1 — de-staged, block-reduced stats ----------------
__global__ __launch_bounds__(128) void k3a_node1(const float* __restrict__ h,
                          const float* __restrict__ nattr,
                          const float* __restrict__ Wh1, const float* __restrict__ bh1) {
    extern __shared__ __align__(16) float sm[];
    float* sW   = sm;                 // NFH*NH
    float* sB   = sW + NFH * NH;      // 72
    float* sSum = sB + NH;            // 144
    float* sSq  = sSum + 144;         // 144

    const int tid = threadIdx.x;
    for (int t = tid; t < NFH * NH; t += 128) sW[t] = Wh1[t];
    if (tid < NH) sB[tid] = bh1[tid];
    for (int t = tid; t < 144; t += 128) { sSum[t] = 0.f; sSq[t] = 0.f; }
    __syncthreads();

    const int lane = tid & 31;
    const int r = tid >> 1, c0 = (tid & 1) * 36;
    const int n = blockIdx.x * 64 + r;
    const bool valid = (n < N_NODES);
    const int ns = valid ? n : 0;

    u64 acc[18];
    {
        const u64* bp = (const u64*)(sB + c0);
#pragma unroll
        for (int c2 = 0; c2 < 18; ++c2) acc[c2] = bp[c2];
    }

    {
        const float4* hr = (const float4*)(h + (size_t)ns * NH);
#pragma unroll 2
        for (int kc = 0; kc < 18; ++kc) {
            float4 f = hr[kc];
            fma_row(acc, sW + (kc * 4 + 0) * NH + c0, f.x);
            fma_row(acc, sW + (kc * 4 + 1) * NH + c0, f.y);
            fma_row(acc, sW + (kc * 4 + 2) * NH + c0, f.z);
            fma_row(acc, sW + (kc * 4 + 3) * NH + c0, f.w);
        }
        const float4* ar = (const float4*)(g_agg_h + (size_t)ns * NH);
#pragma unroll 2
        for (int kc = 0; kc < 18; ++kc) {
            float4 f = ar[kc];
            fma_row(acc, sW + (72 + kc * 4 + 0) * NH + c0, f.x);
            fma_row(acc, sW + (72 + kc * 4 + 1) * NH + c0, f.y);
            fma_row(acc, sW + (72 + kc * 4 + 2) * NH + c0, f.z);
            fma_row(acc, sW + (72 + kc * 4 + 3) * NH + c0, f.w);
        }
        const float4* nr = (const float4*)(nattr + (size_t)ns * 8);
#pragma unroll
        for (int kc = 0; kc < 2; ++kc) {
            float4 f = nr[kc];
            fma_row(acc, sW + (144 + kc * 4 + 0) * NH + c0, f.x);
            fma_row(acc, sW + (144 + kc * 4 + 1) * NH + c0, f.y);
            fma_row(acc, sW + (144 + kc * 4 + 2) * NH + c0, f.z);
            fma_row(acc, sW + (144 + kc * 4 + 3) * NH + c0, f.w);
        }
    }

    float a36[36];
#pragma unroll
    for (int c2 = 0; c2 < 18; ++c2) {
        float2 v = unpack2(acc[c2]);
        a36[2 * c2] = v.x; a36[2 * c2 + 1] = v.y;
    }
#pragma unroll
    for (int c = 0; c < 36; ++c) {
        float s = valid ? a36[c] : 0.f;
        float q = s * s;
#pragma unroll
        for (int msk = 2; msk <= 16; msk <<= 1) {
            s += __shfl_xor_sync(0xffffffffu, s, msk);
            q += __shfl_xor_sync(0xffffffffu, q, msk);
        }
        if (lane < 2) {
            atomicAdd(&sSum[c0 + c], s);
            atomicAdd(&sSq[c0 + c], q);
        }
    }

    if (valid) {
        ulonglong2* zr = (ulonglong2*)(g_zh + (size_t)n * NH + c0);
#pragma unroll
        for (int c2 = 0; c2 < 9; ++c2) {
            ulonglong2 o; o.x = acc[2 * c2]; o.y = acc[2 * c2 + 1];
            zr[c2] = o;
        }
    }
    __syncthreads();

    if (tid < NH) {
        atomicAdd(&g_hsum[tid], sSum[tid]);
        atomicAdd(&g_hsq[tid],  sSq[tid]);
    }
}

// ---------------- K3c: node pass 2 ----------------
__global__ __launch_bounds__(128) void k3c_node2(const float* __restrict__ h, const float* __restrict__ x,
                          const float* __restrict__ Wh2, const float* __restrict__ bh2,
                          float* __restrict__ hout, float* __restrict__ xout) {
    __shared__ __align__(16) float sW[NH * NH];
    __shared__ __align__(16) float sb[NH], sSc[NH], sSh[NH];
    const int tid = threadIdx.x;
    for (int t = tid; t < NH * NH; t += 128) sW[t] = Wh2[t];
    if (tid < NH) { sb[tid] = bh2[tid]; sSc[tid] = g_hscale[tid]; sSh[tid] = g_hshift[tid]; }
    __syncthreads();

    const int half = tid & 1, c0 = half * 36, cp = c0 ^ 36;
    const int n = blockIdx.x * 64 + (tid >> 1);
    if (n >= N_NODES) return;

    u64 acc[18];
#pragma unroll
    for (int c = 0; c < 18; ++c) acc[c] = 0ull;

    {
        const float4* zr = (const float4*)(g_zh + (size_t)n * NH + c0);
        const float4* sc4 = (const float4*)(sSc + c0);
        const float4* sh4 = (const float4*)(sSh + c0);
#pragma unroll 1
        for (int ci = 0; ci < 9; ++ci) {
            float4 z = zr[ci];
            float4 sc = sc4[ci], sh = sh4[ci];
            float a[4];
            a[0] = fmaxf(z.x * sc.x + sh.x, 0.f);
            a[1] = fmaxf(z.y * sc.y + sh.y, 0.f);
            a[2] = fmaxf(z.z * sc.z + sh.z, 0.f);
            a[3] = fmaxf(z.w * sc.w + sh.w, 0.f);
#pragma unroll
            for (int cc = 0; cc < 4; ++cc) {
                int kk = ci * 4 + cc;
                fma_row(acc, sW + (c0 + kk) * NH + c0, a[cc]);
                float fp = __shfl_xor_sync(0xffffffffu, a[cc], 1);
                fma_row(acc, sW + (cp + kk) * NH + c0, fp);
            }
        }
    }

    const float* hr = h + (size_t)n * NH + c0;
    float* orow = hout + (size_t)n * NH + c0;
#pragma unroll
    for (int c4 = 0; c4 < 9; ++c4) {
        float2 v0 = unpack2(acc[2 * c4]);
        float2 v1 = unpack2(acc[2 * c4 + 1]);
        float4 hv = ((const float4*)hr)[c4];
        int c = c0 + c4 * 4;
        ((float4*)orow)[c4] = make_float4(hv.x + v0.x + sb[c + 0],
                                          hv.y + v0.y + sb[c + 1],
                                          hv.z + v1.x + sb[c + 2],
                                          hv.w + v1.y + sb[c + 3]);
    }
    if (half == 0) {
        float4 xi = *(const float4*)(x + 4 * (size_t)n);
        float4 ax = *(const float4*)(g_agg_x + 4 * (size_t)n);
        float inv = 1.f / fmaxf(g_cnt[n], 1.f);
        *(float4*)(xout + 4 * (size_t)n) =
            make_float4(xi.x + ax.x * inv, xi.y + ax.y * inv,
                        xi.z + ax.z * inv, xi.w + ax.w * inv);
    }
}

// ---------------- launch ----------------
extern "C" void kernel_launch(void* const* d_in, const int* in_sizes, int n_in,
                              void* d_out, int out_size) {
    const float* h      = (const float*)d_in[0];
    const float* x      = (const float*)d_in[1];
    const float* nattr  = (const float*)d_in[2];
    const int*   edges  = (const int*)d_in[3];
    const float* We1    = (const float*)d_in[4];
    const float* bn_e_g = (const float*)d_in[5];
    const float* bn_e_b = (const float*)d_in[6];
    const float* We2    = (const float*)d_in[7];
    const float* be2    = (const float*)d_in[8];
    const float* Wh1    = (const float*)d_in[9];
    const float* bh1    = (const float*)d_in[10];
    const float* bn_h_g = (const float*)d_in[11];
    const float* bn_h_b = (const float*)d_in[12];
    const float* Wh2    = (const float*)d_in[13];
    const float* bh2    = (const float*)d_in[14];
    const float* Wx1    = (const float*)d_in[15];
    const float* bx1    = (const float*)d_in[16];
    const float* Wx2    = (const float*)d_in[17];
    const float* Wm     = (const float*)d_in[18];
    const float* bm     = (const float*)d_in[19];

    const int* ei = edges;
    const int* ej = edges + N_EDGES;

    float* out  = (float*)d_out;
    float* hout = out;
    float* xout = out + (size_t)N_NODES * NH;
    float* mout = xout + (size_t)N_NODES * 4;   // z scratch, then m

    int smem3a = (NFH * NH + NH + 288) * 4;
    cudaFuncSetAttribute(k3a_node1, cudaFuncAttributeMaxDynamicSharedMemorySize, smem3a);

    const int GB1 = N_EDGES / 128;          // 12500
    const int EB2 = N_EDGES / 128;          // 12500
    const int NB  = (N_NODES + 63) / 64;    // 782

    k_pre<<<NB, 128>>>(h, We1);                                          // #1
    k1g<<<GB1, 256>>>(x, ei, ej, We1, mout);                             // #2
    kbn_finalize<<<1, 128>>>(bn_e_g, bn_e_b, 1.f / (float)N_EDGES, 0);   // #3
    k2a<<<EB2, 128>>>(ei, We2, be2, Wm, bm, mout);                       // #4 (capture)
    k2b<<<EB2, 128>>>(x, ei, ej, Wx1, bx1, Wx2, mout);                   // #5
    k3a_node1<<<NB, 128, smem3a>>>(h, nattr, Wh1, bh1);                  // #6
    kbn_finalize<<<1, 128>>>(bn_h_g, bn_h_b, 1.f / (float)N_NODES, 1);   // #7
    k3c_node2<<<NB, 128>>>(h, x, Wh2, bh2, hout, xout);                  // #8
}

// round 15
// speedup vs baseline: 1.1530x; 1.1530x over previous
#include <cuda_runtime.h>
#include <math.h>

#define N_NODES 50000
#define N_EDGES 1600000
#define NH      72
#define NFH     152
#define BN_EPS  1e-5f
#define NBUCK   32

typedef unsigned long long u64;

// ---------------- device scratch ----------------
__device__ __align__(16) float g_P[(size_t)N_NODES * NH];
__device__ __align__(16) float g_Q[(size_t)N_NODES * NH];
__device__ __align__(16) float g_agg_h[N_NODES * NH];
__device__ __align__(16) float g_agg_x[N_NODES * 4];
__device__ float g_cnt[N_NODES];
__device__ __align__(16) float g_zh[N_NODES * NH];
__device__ float g_ebuck[NBUCK * 288];
__device__ float g_escale[NH], g_eshift[NH];
__device__ float g_hsum[NH], g_hsq[NH], g_hscale[NH], g_hshift[NH];

__device__ __forceinline__ float psi_f(float p) {
    return copysignf(log1pf(fabsf(p)), p);
}
__device__ __forceinline__ u64 pack2(float f) {
    u64 r; asm("mov.b64 %0, {%1, %1};" : "=l"(r) : "f"(f)); return r;
}
__device__ __forceinline__ u64 pack2f(float a, float b) {
    u64 r; asm("mov.b64 %0, {%1, %2};" : "=l"(r) : "f"(a), "f"(b)); return r;
}
__device__ __forceinline__ void ffma2(u64& d, u64 a, u64 b) {
    asm("fma.rn.f32x2 %0, %1, %2, %0;" : "+l"(d) : "l"(a), "l"(b));
}
__device__ __forceinline__ float2 unpack2(u64 v) {
    float2 r; asm("mov.b64 {%0, %1}, %2;" : "=f"(r.x), "=f"(r.y) : "l"(v)); return r;
}
__device__ __forceinline__ void fma_row(u64* acc, const float* wrow, float f) {
    u64 f2 = pack2(f);
    const ulonglong2* wr = (const ulonglong2*)wrow;
#pragma unroll
    for (int c2 = 0; c2 < 9; ++c2) {
        ulonglong2 w = wr[c2];
        ffma2(acc[2 * c2],     w.x, f2);
        ffma2(acc[2 * c2 + 1], w.y, f2);
    }
}
__device__ __forceinline__ void fma_row2(u64* accA, u64* accB, const float* wrow,
                                         float fA, float fB) {
    u64 a2 = pack2(fA), b2 = pack2(fB);
    const ulonglong2* wr = (const ulonglong2*)wrow;
#pragma unroll
    for (int c2 = 0; c2 < 9; ++c2) {
        ulonglong2 w = wr[c2];
        ffma2(accA[2 * c2],     w.x, a2);
        ffma2(accA[2 * c2 + 1], w.y, a2);
        ffma2(accB[2 * c2],     w.x, b2);
        ffma2(accB[2 * c2 + 1], w.y, b2);
    }
}

// ---------------- K_pre: P/Q precompute + zero accumulators ----------------
__global__ __launch_bounds__(128) void k_pre(const float* __restrict__ h,
                                             const float* __restrict__ We1) {
    __shared__ __align__(16) float sWP[NH * NH];
    __shared__ __align__(16) float sWQ[NH * NH];
    const int tid = threadIdx.x;
    for (int t = tid; t < NH * NH; t += 128) { sWP[t] = We1[t]; sWQ[t] = We1[NH * NH + t]; }

    if (blockIdx.x == 0) {
        for (int t = tid; t < NBUCK * 288; t += 128) g_ebuck[t] = 0.f;
        if (tid < NH) { g_hsum[tid] = 0.f; g_hsq[tid] = 0.f; }
    }
    __syncthreads();

    const int n = blockIdx.x * 64 + (tid >> 1);
    const int half = tid & 1, c0 = half * 36;
    if (n >= N_NODES) return;

    {
        float4 z4 = make_float4(0.f, 0.f, 0.f, 0.f);
        float4* ar = (float4*)(g_agg_h + (size_t)n * NH + c0);
#pragma unroll
        for (int c4 = 0; c4 < 9; ++c4) ar[c4] = z4;
        if (half == 0) {
            *(float4*)(g_agg_x + (size_t)n * 4) = z4;
            g_cnt[n] = 0.f;
        }
    }

    const float4* hr = (const float4*)(h + (size_t)n * NH);
    u64 aP[18], aQ[18];
#pragma unroll
    for (int c = 0; c < 18; ++c) { aP[c] = 0ull; aQ[c] = 0ull; }

#pragma unroll 2
    for (int kc = 0; kc < 18; ++kc) {
        float4 f = hr[kc];
        fma_row(aP, sWP + (kc * 4 + 0) * NH + c0, f.x);
        fma_row(aQ, sWQ + (kc * 4 + 0) * NH + c0, f.x);
        fma_row(aP, sWP + (kc * 4 + 1) * NH + c0, f.y);
        fma_row(aQ, sWQ + (kc * 4 + 1) * NH + c0, f.y);
        fma_row(aP, sWP + (kc * 4 + 2) * NH + c0, f.z);
        fma_row(aQ, sWQ + (kc * 4 + 2) * NH + c0, f.z);
        fma_row(aP, sWP + (kc * 4 + 3) * NH + c0, f.w);
        fma_row(aQ, sWQ + (kc * 4 + 3) * NH + c0, f.w);
    }

    ulonglong2* pr = (ulonglong2*)(g_P + (size_t)n * NH + c0);
    ulonglong2* qr = (ulonglong2*)(g_Q + (size_t)n * NH + c0);
#pragma unroll
    for (int c2 = 0; c2 < 9; ++c2) {
        ulonglong2 o; o.x = aP[2 * c2]; o.y = aP[2 * c2 + 1]; pr[c2] = o;
        ulonglong2 p; p.x = aQ[2 * c2]; p.y = aQ[2 * c2 + 1]; qr[c2] = p;
    }
}

// ---------------- K1g: gather -> z + fused block-reduced BN stats ----------------
__global__ __launch_bounds__(256) void k1g(const float* __restrict__ x,
                                           const int* __restrict__ ei,
                                           const int* __restrict__ ej,
                                           const float* __restrict__ We1,
                                           float* __restrict__ zbuf) {
    __shared__ __align__(16) float sS[2 * NH];
    __shared__ float sSum[144], sSq[144];
    const int tid = threadIdx.x;
    for (int t = tid; t < 2 * NH; t += 256) sS[t] = We1[144 * NH + t];
    if (tid < 144) { sSum[tid] = 0.f; sSq[tid] = 0.f; }
    __syncthreads();

    const int e = tid >> 1, c0 = (tid & 1) * 36;
    const int lane = tid & 31;
    const int ge = blockIdx.x * 128 + e;
    const int i = ei[ge], j = ej[ge];

    float4 xi = *(const float4*)(x + 4 * (size_t)i);
    float4 xj = *(const float4*)(x + 4 * (size_t)j);
    float dx0 = xi.x - xj.x, dx1 = xi.y - xj.y, dx2 = xi.z - xj.z, dx3 = xi.w - xj.w;
    float nw = psi_f(dx0 * dx0 - dx1 * dx1 - dx2 * dx2 - dx3 * dx3);
    float dw = psi_f(xi.x * xj.x - xi.y * xj.y - xi.z * xj.z - xi.w * xj.w);

    const float4* Pr = (const float4*)(g_P + (size_t)i * NH + c0);
    const float4* Qr = (const float4*)(g_Q + (size_t)j * NH + c0);
    float4* zr = (float4*)(zbuf + (size_t)ge * NH + c0);

    float z36[36];
#pragma unroll
    for (int c4 = 0; c4 < 9; ++c4) {
        float4 p = Pr[c4], q = Qr[c4];
        int c = c0 + c4 * 4;
        float z0 = p.x + q.x + nw * sS[c + 0] + dw * sS[NH + c + 0];
        float z1 = p.y + q.y + nw * sS[c + 1] + dw * sS[NH + c + 1];
        float z2 = p.z + q.z + nw * sS[c + 2] + dw * sS[NH + c + 2];
        float z3 = p.w + q.w + nw * sS[c + 3] + dw * sS[NH + c + 3];
        z36[c4 * 4 + 0] = z0; z36[c4 * 4 + 1] = z1;
        z36[c4 * 4 + 2] = z2; z36[c4 * 4 + 3] = z3;
        zr[c4] = make_float4(z0, z1, z2, z3);
    }

#pragma unroll
    for (int c = 0; c < 36; ++c) {
        float s = z36[c];
        float q = s * s;
#pragma unroll
        for (int msk = 2; msk <= 16; msk <<= 1) {
            s += __shfl_xor_sync(0xffffffffu, s, msk);
            q += __shfl_xor_sync(0xffffffffu, q, msk);
        }
        if (lane < 2) {
            atomicAdd(&sSum[c0 + c], s);
            atomicAdd(&sSq[c0 + c], q);
        }
    }
    __syncthreads();

    if (tid < 288) {
        float v = (tid < 144) ? sSum[tid] : sSq[tid - 144];
        atomicAdd(&g_ebuck[(blockIdx.x & (NBUCK - 1)) * 288 + tid], v);
    }
}

// ---------------- BN finalize ----------------
__global__ void kbn_finalize(const float* __restrict__ gamma, const float* __restrict__ beta,
                             float invM, int which) {
    int c = threadIdx.x;
    if (c >= NH) return;
    float s_ = 0.f, q_ = 0.f;
    if (which == 0) {
#pragma unroll 4
        for (int b = 0; b < NBUCK; ++b) {
            s_ += g_ebuck[b * 288 + c];
            q_ += g_ebuck[b * 288 + 144 + c];
        }
    } else {
        s_ = g_hsum[c]; q_ = g_hsq[c];
    }
    float mu  = s_ * invM;
    float var = q_ * invM - mu * mu;
    float sc  = gamma[c] * rsqrtf(var + BN_EPS);
    if (which == 0) { g_escale[c] = sc; g_eshift[c] = beta[c] - mu * sc; }
    else            { g_hscale[c] = sc; g_hshift[c] = beta[c] - mu * sc; }
}

// ---------------- K2: fused, 2 edges/thread, dual weight buffers (no mid-kernel swap) ----------------
__global__ __launch_bounds__(128) void k2(const float* __restrict__ x,
        const int* __restrict__ ei, const int* __restrict__ ej,
        const float* __restrict__ We2, const float* __restrict__ be2,
        const float* __restrict__ Wm,  const float* __restrict__ bm,
        const float* __restrict__ Wx1, const float* __restrict__ bx1,
        const float* __restrict__ Wx2,
        float* mout /* z in, m out */) {
    __shared__ __align__(16) float sW2[NH * NH];
    __shared__ __align__(16) float sWx[NH * NH];
    __shared__ __align__(16) float sSc[NH], sSh[NH], sBe[NH], sWm[NH], sBx[NH], sWx2[NH];

    const int tid = threadIdx.x;
    for (int t = tid; t < NH * NH; t += 128) { sW2[t] = We2[t]; sWx[t] = Wx1[t]; }
    if (tid < NH) {
        sSc[tid] = g_escale[tid]; sSh[tid] = g_eshift[tid];
        sBe[tid] = be2[tid];  sWm[tid]  = Wm[tid];
        sBx[tid] = bx1[tid];  sWx2[tid] = Wx2[tid];
    }
    __syncthreads();

    const int half = tid & 1, c0 = half * 36, cp = c0 ^ 36;
    const int r = tid >> 1;
    const int geA = blockIdx.x * 128 + r;
    const int geB = geA + 64;
    const int iA = ei[geA], iB = ei[geB];

    u64 acc0[18], acc1[18];
#pragma unroll
    for (int c = 0; c < 18; ++c) { acc0[c] = 0ull; acc1[c] = 0ull; }

    // GEMM1: stream z lazily, consume each feature immediately (own + partner rows)
    {
        const float4* zA4 = (const float4*)(mout + (size_t)geA * NH + c0);
        const float4* zB4 = (const float4*)(mout + (size_t)geB * NH + c0);
        const float4* sc4 = (const float4*)(sSc + c0);
        const float4* sh4 = (const float4*)(sSh + c0);
#pragma unroll 1
        for (int ci = 0; ci < 9; ++ci) {
            float4 za = zA4[ci], zb = zB4[ci];
            float4 sc = sc4[ci], sh = sh4[ci];
            float aA[4], aB[4];
            aA[0] = fmaxf(za.x * sc.x + sh.x, 0.f);
            aA[1] = fmaxf(za.y * sc.y + sh.y, 0.f);
            aA[2] = fmaxf(za.z * sc.z + sh.z, 0.f);
            aA[3] = fmaxf(za.w * sc.w + sh.w, 0.f);
            aB[0] = fmaxf(zb.x * sc.x + sh.x, 0.f);
            aB[1] = fmaxf(zb.y * sc.y + sh.y, 0.f);
            aB[2] = fmaxf(zb.z * sc.z + sh.z, 0.f);
            aB[3] = fmaxf(zb.w * sc.w + sh.w, 0.f);
#pragma unroll
            for (int cc = 0; cc < 4; ++cc) {
                int kk = ci * 4 + cc;
                fma_row2(acc0, acc1, sW2 + (c0 + kk) * NH + c0, aA[cc], aB[cc]);
                float fA = __shfl_xor_sync(0xffffffffu, aA[cc], 1);
                float fB = __shfl_xor_sync(0xffffffffu, aB[cc], 1);
                fma_row2(acc0, acc1, sW2 + (cp + kk) * NH + c0, fA, fB);
            }
        }
    }

    // epilogue: e = relu(acc + be2); gate
    float pd0 = 0.f, pd1 = 0.f;
#pragma unroll
    for (int c2 = 0; c2 < 18; ++c2) {
        float2 v0 = unpack2(acc0[c2]);
        float2 v1 = unpack2(acc1[c2]);
        int c = c0 + 2 * c2;
        float e00 = fmaxf(v0.x + sBe[c + 0], 0.f);
        float e01 = fmaxf(v0.y + sBe[c + 1], 0.f);
        float e10 = fmaxf(v1.x + sBe[c + 0], 0.f);
        float e11 = fmaxf(v1.y + sBe[c + 1], 0.f);
        acc0[c2] = pack2f(e00, e01);
        acc1[c2] = pack2f(e10, e11);
        pd0 += e00 * sWm[c + 0] + e01 * sWm[c + 1];
        pd1 += e10 * sWm[c + 0] + e11 * sWm[c + 1];
    }
    pd0 += __shfl_xor_sync(0xffffffffu, pd0, 1);
    pd1 += __shfl_xor_sync(0xffffffffu, pd1, 1);
    float bmv = bm[0];
    float w0 = 1.f / (1.f + expf(-(pd0 + bmv)));
    float w1 = 1.f / (1.f + expf(-(pd1 + bmv)));

    // m = e*w -> gmem write + aggregation atomics (acc freed after this)
    {
        float* mrA = mout + (size_t)geA * NH + c0;
        float* mrB = mout + (size_t)geB * NH + c0;
        float* arA = g_agg_h + (size_t)iA * NH + c0;
        float* arB = g_agg_h + (size_t)iB * NH + c0;
#pragma unroll
        for (int c4 = 0; c4 < 9; ++c4) {
            float2 a0 = unpack2(acc0[2 * c4]);
            float2 a1 = unpack2(acc0[2 * c4 + 1]);
            float2 b0 = unpack2(acc1[2 * c4]);
            float2 b1 = unpack2(acc1[2 * c4 + 1]);
            float4 mA = make_float4(a0.x * w0, a0.y * w0, a1.x * w0, a1.y * w0);
            float4 mB = make_float4(b0.x * w1, b0.y * w1, b1.x * w1, b1.y * w1);
            ((float4*)mrA)[c4] = mA;
            ((float4*)mrB)[c4] = mB;
            atomicAdd((float4*)(arA + c4 * 4), mA);
            atomicAdd((float4*)(arB + c4 * 4), mB);
        }
        if (half == 0) {
            atomicAdd(&g_cnt[iA], 1.f);
            atomicAdd(&g_cnt[iB], 1.f);
        }
    }

    // GEMM2: stream m back (own writes -> L1/L2 hits), weights already resident
#pragma unroll
    for (int c = 0; c < 18; ++c) { acc0[c] = 0ull; acc1[c] = 0ull; }
    {
        const float4* mA4 = (const float4*)(mout + (size_t)geA * NH + c0);
        const float4* mB4 = (const float4*)(mout + (size_t)geB * NH + c0);
#pragma unroll 1
        for (int ci = 0; ci < 9; ++ci) {
            float4 ma = mA4[ci], mb = mB4[ci];
            float aA[4] = {ma.x, ma.y, ma.z, ma.w};
            float aB[4] = {mb.x, mb.y, mb.z, mb.w};
#pragma unroll
            for (int cc = 0; cc < 4; ++cc) {
                int kk = ci * 4 + cc;
                fma_row2(acc0, acc1, sWx + (c0 + kk) * NH + c0, aA[cc], aB[cc]);
                float fA = __shfl_xor_sync(0xffffffffu, aA[cc], 1);
                float fB = __shfl_xor_sync(0xffffffffu, aB[cc], 1);
                fma_row2(acc0, acc1, sWx + (cp + kk) * NH + c0, fA, fB);
            }
        }
    }

    float px0 = 0.f, px1 = 0.f;
#pragma unroll
    for (int c2 = 0; c2 < 18; ++c2) {
        float2 v0 = unpack2(acc0[c2]);
        float2 v1 = unpack2(acc1[c2]);
        int c = c0 + 2 * c2;
        px0 += fmaxf(v0.x + sBx[c + 0], 0.f) * sWx2[c + 0];
        px0 += fmaxf(v0.y + sBx[c + 1], 0.f) * sWx2[c + 1];
        px1 += fmaxf(v1.x + sBx[c + 0], 0.f) * sWx2[c + 0];
        px1 += fmaxf(v1.y + sBx[c + 1], 0.f) * sWx2[c + 1];
    }
    px0 += __shfl_xor_sync(0xffffffffu, px0, 1);
    px1 += __shfl_xor_sync(0xffffffffu, px1, 1);

    if (half == 0) {
        {
            const int j = ej[geA];
            float4 xi = *(const float4*)(x + 4 * (size_t)iA);
            float4 xj = *(const float4*)(x + 4 * (size_t)j);
            float t0 = fminf(fmaxf((xi.x - xj.x) * px0, -100.f), 100.f);
            float t1 = fminf(fmaxf((xi.y - xj.y) * px0, -100.f), 100.f);
            float t2 = fminf(fmaxf((xi.z - xj.z) * px0, -100.f), 100.f);
            float t3 = fminf(fmaxf((xi.w - xj.w) * px0, -100.f), 100.f);
            atomicAdd((float4*)&g_agg_x[(size_t)iA * 4], make_float4(t0, t1, t2, t3));
        }
        {
            const int j = ej[geB];
            float4 xi = *(const float4*)(x + 4 * (size_t)iB);
            float4 xj = *(const float4*)(x + 4 * (size_t)j);
            float t0 = fminf(fmaxf((xi.x - xj.x) * px1, -100.f), 100.f);
            float t1 = fminf(fmaxf((xi.y - xj.y) * px1, -100.f), 100.f);
            float t2 = fminf(fmaxf((xi.z - xj.z) * px1, -100.f), 100.f);
            float t3 = fminf(fmaxf((xi.w - xj.w) * px1, -100.f), 100.f);
            atomicAdd((float4*)&g_agg_x[(size_t)iB * 4], make_float4(t0, t1, t2, t3));
        }
    }
}

// ---------------- K3a: node pass 1 — de-staged, block-reduced stats ----------------
__global__ __launch_bounds__(128) void k3a_node1(const float* __restrict__ h,
                          const float* __restrict__ nattr,
                          const float* __restrict__ Wh1, const float* __restrict__ bh1) {
    extern __shared__ __align__(16) float sm[];
    float* sW   = sm;                 // NFH*NH
    float* sB   = sW + NFH * NH;      // 72
    float* sSum = sB + NH;            // 144
    float* sSq  = sSum + 144;         // 144

    const int tid = threadIdx.x;
    for (int t = tid; t < NFH * NH; t += 128) sW[t] = Wh1[t];
    if (tid < NH) sB[tid] = bh1[tid];
    for (int t = tid; t < 144; t += 128) { sSum[t] = 0.f; sSq[t] = 0.f; }
    __syncthreads();

    const int lane = tid & 31;
    const int r = tid >> 1, c0 = (tid & 1) * 36;
    const int n = blockIdx.x * 64 + r;
    const bool valid = (n < N_NODES);
    const int ns = valid ? n : 0;

    u64 acc[18];
    {
        const u64* bp = (const u64*)(sB + c0);
#pragma unroll
        for (int c2 = 0; c2 < 18; ++c2) acc[c2] = bp[c2];
    }

    {
        const float4* hr = (const float4*)(h + (size_t)ns * NH);
#pragma unroll 2
        for (int kc = 0; kc < 18; ++kc) {
            float4 f = hr[kc];
            fma_row(acc, sW + (kc * 4 + 0) * NH + c0, f.x);
            fma_row(acc, sW + (kc * 4 + 1) * NH + c0, f.y);
            fma_row(acc, sW + (kc * 4 + 2) * NH + c0, f.z);
            fma_row(acc, sW + (kc * 4 + 3) * NH + c0, f.w);
        }
        const float4* ar = (const float4*)(g_agg_h + (size_t)ns * NH);
#pragma unroll 2
        for (int kc = 0; kc < 18; ++kc) {
            float4 f = ar[kc];
            fma_row(acc, sW + (72 + kc * 4 + 0) * NH + c0, f.x);
            fma_row(acc, sW + (72 + kc * 4 + 1) * NH + c0, f.y);
            fma_row(acc, sW + (72 + kc * 4 + 2) * NH + c0, f.z);
            fma_row(acc, sW + (72 + kc * 4 + 3) * NH + c0, f.w);
        }
        const float4* nr = (const float4*)(nattr + (size_t)ns * 8);
#pragma unroll
        for (int kc = 0; kc < 2; ++kc) {
            float4 f = nr[kc];
            fma_row(acc, sW + (144 + kc * 4 + 0) * NH + c0, f.x);
            fma_row(acc, sW + (144 + kc * 4 + 1) * NH + c0, f.y);
            fma_row(acc, sW + (144 + kc * 4 + 2) * NH + c0, f.z);
            fma_row(acc, sW + (144 + kc * 4 + 3) * NH + c0, f.w);
        }
    }

    float a36[36];
#pragma unroll
    for (int c2 = 0; c2 < 18; ++c2) {
        float2 v = unpack2(acc[c2]);
        a36[2 * c2] = v.x; a36[2 * c2 + 1] = v.y;
    }
#pragma unroll
    for (int c = 0; c < 36; ++c) {
        float s = valid ? a36[c] : 0.f;
        float q = s * s;
#pragma unroll
        for (int msk = 2; msk <= 16; msk <<= 1) {
            s += __shfl_xor_sync(0xffffffffu, s, msk);
            q += __shfl_xor_sync(0xffffffffu, q, msk);
        }
        if (lane < 2) {
            atomicAdd(&sSum[c0 + c], s);
            atomicAdd(&sSq[c0 + c], q);
        }
    }

    if (valid) {
        ulonglong2* zr = (ulonglong2*)(g_zh + (size_t)n * NH + c0);
#pragma unroll
        for (int c2 = 0; c2 < 9; ++c2) {
            ulonglong2 o; o.x = acc[2 * c2]; o.y = acc[2 * c2 + 1];
            zr[c2] = o;
        }
    }
    __syncthreads();

    if (tid < NH) {
        atomicAdd(&g_hsum[tid], sSum[tid]);
        atomicAdd(&g_hsq[tid],  sSq[tid]);
    }
}

// ---------------- K3c: node pass 2 ----------------
__global__ __launch_bounds__(128) void k3c_node2(const float* __restrict__ h, const float* __restrict__ x,
                          const float* __restrict__ Wh2, const float* __restrict__ bh2,
                          float* __restrict__ hout, float* __restrict__ xout) {
    __shared__ __align__(16) float sW[NH * NH];
    __shared__ __align__(16) float sb[NH], sSc[NH], sSh[NH];
    const int tid = threadIdx.x;
    for (int t = tid; t < NH * NH; t += 128) sW[t] = Wh2[t];
    if (tid < NH) { sb[tid] = bh2[tid]; sSc[tid] = g_hscale[tid]; sSh[tid] = g_hshift[tid]; }
    __syncthreads();

    const int half = tid & 1, c0 = half * 36, cp = c0 ^ 36;
    const int n = blockIdx.x * 64 + (tid >> 1);
    if (n >= N_NODES) return;

    u64 acc[18];
#pragma unroll
    for (int c = 0; c < 18; ++c) acc[c] = 0ull;

    {
        const float4* zr = (const float4*)(g_zh + (size_t)n * NH + c0);
        const float4* sc4 = (const float4*)(sSc + c0);
        const float4* sh4 = (const float4*)(sSh + c0);
#pragma unroll 1
        for (int ci = 0; ci < 9; ++ci) {
            float4 z = zr[ci];
            float4 sc = sc4[ci], sh = sh4[ci];
            float a[4];
            a[0] = fmaxf(z.x * sc.x + sh.x, 0.f);
            a[1] = fmaxf(z.y * sc.y + sh.y, 0.f);
            a[2] = fmaxf(z.z * sc.z + sh.z, 0.f);
            a[3] = fmaxf(z.w * sc.w + sh.w, 0.f);
#pragma unroll
            for (int cc = 0; cc < 4; ++cc) {
                int kk = ci * 4 + cc;
                fma_row(acc, sW + (c0 + kk) * NH + c0, a[cc]);
                float fp = __shfl_xor_sync(0xffffffffu, a[cc], 1);
                fma_row(acc, sW + (cp + kk) * NH + c0, fp);
            }
        }
    }

    const float* hr = h + (size_t)n * NH + c0;
    float* orow = hout + (size_t)n * NH + c0;
#pragma unroll
    for (int c4 = 0; c4 < 9; ++c4) {
        float2 v0 = unpack2(acc[2 * c4]);
        float2 v1 = unpack2(acc[2 * c4 + 1]);
        float4 hv = ((const float4*)hr)[c4];
        int c = c0 + c4 * 4;
        ((float4*)orow)[c4] = make_float4(hv.x + v0.x + sb[c + 0],
                                          hv.y + v0.y + sb[c + 1],
                                          hv.z + v1.x + sb[c + 2],
                                          hv.w + v1.y + sb[c + 3]);
    }
    if (half == 0) {
        float4 xi = *(const float4*)(x + 4 * (size_t)n);
        float4 ax = *(const float4*)(g_agg_x + 4 * (size_t)n);
        float inv = 1.f / fmaxf(g_cnt[n], 1.f);
        *(float4*)(xout + 4 * (size_t)n) =
            make_float4(xi.x + ax.x * inv, xi.y + ax.y * inv,
                        xi.z + ax.z * inv, xi.w + ax.w * inv);
    }
}

// ---------------- launch ----------------
extern "C" void kernel_launch(void* const* d_in, const int* in_sizes, int n_in,
                              void* d_out, int out_size) {
    const float* h      = (const float*)d_in[0];
    const float* x      = (const float*)d_in[1];
    const float* nattr  = (const float*)d_in[2];
    const int*   edges  = (const int*)d_in[3];
    const float* We1    = (const float*)d_in[4];
    const float* bn_e_g = (const float*)d_in[5];
    const float* bn_e_b = (const float*)d_in[6];
    const float* We2    = (const float*)d_in[7];
    const float* be2    = (const float*)d_in[8];
    const float* Wh1    = (const float*)d_in[9];
    const float* bh1    = (const float*)d_in[10];
    const float* bn_h_g = (const float*)d_in[11];
    const float* bn_h_b = (const float*)d_in[12];
    const float* Wh2    = (const float*)d_in[13];
    const float* bh2    = (const float*)d_in[14];
    const float* Wx1    = (const float*)d_in[15];
    const float* bx1    = (const float*)d_in[16];
    const float* Wx2    = (const float*)d_in[17];
    const float* Wm     = (const float*)d_in[18];
    const float* bm     = (const float*)d_in[19];

    const int* ei = edges;
    const int* ej = edges + N_EDGES;

    float* out  = (float*)d_out;
    float* hout = out;
    float* xout = out + (size_t)N_NODES * NH;
    float* mout = xout + (size_t)N_NODES * 4;   // z scratch, then m

    int smem3a = (NFH * NH + NH + 288) * 4;
    cudaFuncSetAttribute(k3a_node1, cudaFuncAttributeMaxDynamicSharedMemorySize, smem3a);

    const int GB1 = N_EDGES / 128;          // 12500
    const int EB2 = N_EDGES / 128;          // 12500
    const int NB  = (N_NODES + 63) / 64;    // 782

    k_pre<<<NB, 128>>>(h, We1);                                          // #1
    k1g<<<GB1, 256>>>(x, ei, ej, We1, mout);                             // #2
    kbn_finalize<<<1, 128>>>(bn_e_g, bn_e_b, 1.f / (float)N_EDGES, 0);   // #3
    k2<<<EB2, 128>>>(x, ei, ej, We2, be2, Wm, bm, Wx1, bx1, Wx2, mout);  // #4 (capture)
    k3a_node1<<<NB, 128, smem3a>>>(h, nattr, Wh1, bh1);                  // #5
    kbn_finalize<<<1, 128>>>(bn_h_g, bn_h_b, 1.f / (float)N_NODES, 1);   // #6
    k3c_node2<<<NB, 128>>>(h, x, Wh2, bh2, hout, xout);                  // #7
}